// round 13
// baseline (speedup 1.0000x reference)
#include <cuda_runtime.h>
#include <cuda_bf16.h>
#include <math.h>
#include <cstdint>

#define NB      4096
#define PAD     (NB / 2)
#define BATCH   8192
#define T       512
#define NWARP   (T / 32)          // 16
#define GRID_N  608               // 152 SMs (GB300) * 4 CTAs/SM — balanced wave

// Row-invariant precomputed data.
__device__ float          g_p[NB];    // sigmoid(logits)
__device__ __nv_bfloat16  g_lb[NB];   // logits (bf16, used only for weighted sum)
__device__ float          g_C;        // sum_j log_sigmoid(-logits[j])

// ---------------------------------------------------------------------------
// Precompute: single block, fast path. __expf sigmoid; C via product trick.
// Triggers programmatic launch completion as soon as the table is written so
// the PDL secondary releases without waiting for this grid's full teardown.
// ---------------------------------------------------------------------------
__global__ __launch_bounds__(1024)
void precompute_kernel(const float* __restrict__ logits) {
    __shared__ float s_red[32];
    const int tid = threadIdx.x;

    const float4* __restrict__ l4 = (const float4*)logits;
    const float4 L = __ldg(&l4[tid]);          // 1024 threads * 4 = 4096 elems

    float p0 = 1.0f / (1.0f + __expf(-L.x));
    float p1 = 1.0f / (1.0f + __expf(-L.y));
    float p2 = 1.0f / (1.0f + __expf(-L.z));
    float p3 = 1.0f / (1.0f + __expf(-L.w));
    ((float4*)g_p)[tid] = make_float4(p0, p1, p2, p3);

    __nv_bfloat162* lbp = (__nv_bfloat162*)g_lb;
    lbp[2 * tid]     = __floats2bfloat162_rn(L.x, L.y);
    lbp[2 * tid + 1] = __floats2bfloat162_rn(L.z, L.w);

    float c = __logf((1.0f - p0) * (1.0f - p1) * (1.0f - p2) * (1.0f - p3));
    #pragma unroll
    for (int o = 16; o; o >>= 1) c += __shfl_xor_sync(0xFFFFFFFFu, c, o);
    if ((tid & 31) == 0) s_red[tid >> 5] = c;
    __syncthreads();
    if (tid < 32) {
        float v = s_red[tid];
        #pragma unroll
        for (int o = 16; o; o >>= 1) v += __shfl_xor_sync(0xFFFFFFFFu, v, o);
        if (tid == 0) g_C = v;
    }
    __syncthreads();                       // all table writes done
    cudaTriggerProgrammaticLaunchCompletion();
}

// ---------------------------------------------------------------------------
// Main fused kernel: EXACT R4/R11/R12 structure, PDL entry sync.
// ---------------------------------------------------------------------------
__global__ __launch_bounds__(T, 4)
void fused_kernel(const float* __restrict__ u,
                  const int*   __restrict__ shift,
                  float*       __restrict__ masks,
                  float*       __restrict__ log_probs) {
    __shared__ __align__(16) unsigned char s_g[2][NB + 16];
    __shared__ float s_red[2][NWARP];

    // Wait for precompute_kernel's table writes (released at its trigger).
    cudaGridDependencySynchronize();

    const int tid  = threadIdx.x;
    const int lane = tid & 31;
    const int warp = tid >> 5;

    const float4* __restrict__ p4  = (const float4*)g_p;
    const uint2*  __restrict__ lb2 = (const uint2*)g_lb;   // 4 bf16 per uint2

    int buf = 0;
    for (int b = blockIdx.x; b < BATCH; b += GRID_N, buf ^= 1) {
        const float4* __restrict__ u4 = (const float4*)(u + (size_t)b * NB);

        float4 ua = __ldcs(&u4[tid]);
        float4 ub = __ldcs(&u4[tid + T]);
        float4 pa = p4[tid];
        float4 pb = p4[tid + T];
        uint2  la = lb2[tid];
        uint2  lb = lb2[tid + T];

        __nv_bfloat162 la0 = *reinterpret_cast<__nv_bfloat162*>(&la.x);
        __nv_bfloat162 la1 = *reinterpret_cast<__nv_bfloat162*>(&la.y);
        __nv_bfloat162 lb0 = *reinterpret_cast<__nv_bfloat162*>(&lb.x);
        __nv_bfloat162 lb1 = *reinterpret_cast<__nv_bfloat162*>(&lb.y);

        uint32_t wa = (ua.x < pa.x ? 0x01u      : 0u)
                    | (ua.y < pa.y ? 0x100u     : 0u)
                    | (ua.z < pa.z ? 0x10000u   : 0u)
                    | (ua.w < pa.w ? 0x1000000u : 0u);
        uint32_t wb = (ub.x < pb.x ? 0x01u      : 0u)
                    | (ub.y < pb.y ? 0x100u     : 0u)
                    | (ub.z < pb.z ? 0x10000u   : 0u)
                    | (ub.w < pb.w ? 0x1000000u : 0u);
        float acc = (ua.x < pa.x ? __low2float(la0)  : 0.0f)
                  + (ua.y < pa.y ? __high2float(la0) : 0.0f)
                  + (ua.z < pa.z ? __low2float(la1)  : 0.0f)
                  + (ua.w < pa.w ? __high2float(la1) : 0.0f)
                  + (ub.x < pb.x ? __low2float(lb0)  : 0.0f)
                  + (ub.y < pb.y ? __high2float(lb0) : 0.0f)
                  + (ub.z < pb.z ? __low2float(lb1)  : 0.0f)
                  + (ub.w < pb.w ? __high2float(lb1) : 0.0f);

        uint32_t* sw = (uint32_t*)&s_g[buf][0];
        sw[tid]     = wa;
        sw[tid + T] = wb;

        // ---- block reduction -> log_probs[b] --------------------------------
        #pragma unroll
        for (int o = 16; o; o >>= 1) acc += __shfl_xor_sync(0xFFFFFFFFu, acc, o);
        if (lane == 0) s_red[buf][warp] = acc;
        __syncthreads();
        if (warp == 0) {
            float v = (lane < NWARP) ? s_red[buf][lane] : 0.0f;
            #pragma unroll
            for (int o = 8; o; o >>= 1) v += __shfl_xor_sync(0xFFFFFFFFu, v, o);
            if (lane == 0) log_probs[b] = v + g_C;
        }

        // ---- reflect-shift gather -> 2x STG.128 ------------------------------
        const int sh = __ldg(&shift[b]);
        float4* __restrict__ out4 = (float4*)(masks + (size_t)b * NB);

        #pragma unroll
        for (int it = 0; it < 2; ++it) {
            const int idx  = tid + it * T;
            const int base = sh + 4 * idx - PAD;
            float4 o4;
            if (base >= 0 && base <= NB - 4) {
                const int wi = base >> 2;
                uint32_t w0 = sw[wi], w1 = sw[wi + 1];        // wi+1 within padding
                uint32_t pk = __byte_perm(w0, w1, 0x3210 + (base & 3) * 0x1111);
                o4.x = __int_as_float((pk & 0xFFu)         * 0x3F800000u);
                o4.y = __int_as_float(((pk >> 8)  & 0xFFu) * 0x3F800000u);
                o4.z = __int_as_float(((pk >> 16) & 0xFFu) * 0x3F800000u);
                o4.w = __int_as_float(((pk >> 24) & 0xFFu) * 0x3F800000u);
            } else {
                float r[4];
                #pragma unroll
                for (int k = 0; k < 4; k++) {
                    int s = base + k;
                    s = (s < 0) ? -s : s;
                    s = (s >= NB) ? (2 * (NB - 1) - s) : s;
                    r[k] = (float)s_g[buf][s];
                }
                o4 = make_float4(r[0], r[1], r[2], r[3]);
            }
            __stcs(&out4[idx], o4);
        }
        // double buffering removes the need for a trailing barrier per row
    }
}

// ---------------------------------------------------------------------------
extern "C" void kernel_launch(void* const* d_in, const int* in_sizes, int n_in,
                              void* d_out, int out_size) {
    const float* logits = (const float*)d_in[0];   // (NB,)
    const float* u      = (const float*)d_in[1];   // (B, NB)
    const int*   shift  = (const int*)  d_in[2];   // (B,)

    float* masks     = (float*)d_out;                       // (B, 1, NB)
    float* log_probs = (float*)d_out + (size_t)BATCH * NB;  // (B,)

    precompute_kernel<<<1, 1024>>>(logits);

    // Programmatic dependent launch: fused_kernel's CTAs are scheduled while
    // precompute_kernel still runs; release happens at its trigger.
    cudaLaunchConfig_t cfg = {};
    cfg.gridDim  = dim3(GRID_N, 1, 1);
    cfg.blockDim = dim3(T, 1, 1);
    cfg.dynamicSmemBytes = 0;
    cfg.stream = 0;
    cudaLaunchAttribute attr[1];
    attr[0].id = cudaLaunchAttributeProgrammaticStreamSerialization;
    attr[0].val.programmaticStreamSerializationAllowed = 1;
    cfg.attrs = attr;
    cfg.numAttrs = 1;
    cudaLaunchKernelEx(&cfg, fused_kernel, u, shift, masks, log_probs);
}